// round 2
// baseline (speedup 1.0000x reference)
#include <cuda_runtime.h>
#include <cstdint>
#include <cstddef>

// ---------------- problem constants ----------------
static constexpr int Bm = 1024;     // batch rows
static constexpr int Dk = 512;      // feature dim (K)
static constexpr int Cn = 100000;   // classes (N)
static constexpr float S_s = 30.0f;
static constexpr float M_m = 0.4f;

// ---------------- device scratch (no runtime allocation allowed) ----------------
__device__ float g_Xn[Bm * Dk];                       // normalized x
__device__ float g_winv[Cn];                          // 1 / ||W[:,c]||
__device__ float g_rowsum[Bm];                        // sum_c exp(S*cos)
__device__ float g_cos_scratch[(size_t)Bm * (size_t)Cn]; // only used if d_out can't hold cossim

// ---------------- helpers ----------------
__device__ __forceinline__ float to_tf32(float x) {
    uint32_t u;
    asm("cvt.rna.tf32.f32 %0, %1;" : "=r"(u) : "f"(x));
    return __uint_as_float(u);
}

__device__ __forceinline__ void mma8(float* d, const uint32_t* a, const uint32_t* b) {
    asm volatile(
        "mma.sync.aligned.m16n8k8.row.col.f32.tf32.tf32.f32 "
        "{%0,%1,%2,%3}, {%4,%5,%6,%7}, {%8,%9}, {%0,%1,%2,%3};\n"
        : "+f"(d[0]), "+f"(d[1]), "+f"(d[2]), "+f"(d[3])
        : "r"(a[0]), "r"(a[1]), "r"(a[2]), "r"(a[3]), "r"(b[0]), "r"(b[1]));
}

// ---------------- kernel 1: L2-normalize rows of x; zero rowsum ----------------
__global__ void normalize_x_kernel(const float* __restrict__ x) {
    const int b = blockIdx.x;           // 1024 blocks
    const int t = threadIdx.x;          // 128 threads
    float4 v = reinterpret_cast<const float4*>(x + (size_t)b * Dk)[t];
    float ss = v.x * v.x + v.y * v.y + v.z * v.z + v.w * v.w;
    #pragma unroll
    for (int o = 16; o > 0; o >>= 1) ss += __shfl_xor_sync(0xffffffffu, ss, o);
    __shared__ float ws[4];
    if ((t & 31) == 0) ws[t >> 5] = ss;
    __syncthreads();
    const float tot = ws[0] + ws[1] + ws[2] + ws[3];
    const float inv = 1.0f / fmaxf(sqrtf(tot), 1e-12f);
    float4 o4;
    o4.x = v.x * inv; o4.y = v.y * inv; o4.z = v.z * inv; o4.w = v.w * inv;
    reinterpret_cast<float4*>(g_Xn + (size_t)b * Dk)[t] = o4;
    if (t == 0) g_rowsum[b] = 0.0f;
}

// ---------------- kernel 2: per-column inverse norms of W ----------------
__global__ void wnorm_kernel(const float* __restrict__ Wp) {
    const int c = blockIdx.x * blockDim.x + threadIdx.x;
    if (c >= Cn) return;
    float ss = 0.0f;
    #pragma unroll 8
    for (int d = 0; d < Dk; ++d) {
        const float w = Wp[(size_t)d * Cn + c];
        ss = fmaf(w, w, ss);
    }
    g_winv[c] = 1.0f / fmaxf(sqrtf(ss), 1e-12f);
}

// ---------------- kernel 3: TF32 GEMM + fused AM-Softmax epilogue ----------------
#define BMT 128
#define BNT 128
#define BKT 16
#define LDA 20      // BK + 4  -> conflict-free A fragment loads
#define LDB 136     // BN + 8  -> conflict-free B fragment loads

__global__ void __launch_bounds__(256, 2)
gemm_cos_kernel(const float* __restrict__ Wp, float* __restrict__ outp) {
    __shared__ __align__(16) float As[2][BMT * LDA];
    __shared__ __align__(16) float Bs[2][BKT * LDB];

    float* __restrict__ outc = outp ? outp : g_cos_scratch;

    const int tid  = threadIdx.x;
    const int lane = tid & 31;
    const int g    = lane >> 2;
    const int t    = lane & 3;
    const int warp = tid >> 5;
    const int wm   = warp & 1;    // 2 warps in M
    const int wn   = warp >> 1;   // 4 warps in N
    const int bN   = blockIdx.x * BNT;
    const int bM   = blockIdx.y * BMT;

    // global-load coordinates (per thread)
    const int arow = tid >> 2;          // 0..63 (+64 for second chunk)
    const int ac4  = (tid & 3) * 4;     // k offset within BK
    const int bkr  = tid >> 5;          // 0..7  (+8 for second chunk)
    const int bc4  = (tid & 31) * 4;    // col offset within BN
    const int bcol = bN + bc4;
    const bool bvalid = (bcol < Cn);

    float acc[4][4][4];
    #pragma unroll
    for (int i = 0; i < 4; ++i)
        #pragma unroll
        for (int j = 0; j < 4; ++j)
            #pragma unroll
            for (int k = 0; k < 4; ++k) acc[i][j][k] = 0.0f;

    const float* Abase = g_Xn + (size_t)bM * Dk;

    float4 ra0, ra1, rb0, rb1;
    // prologue: load k-chunk 0
    ra0 = *reinterpret_cast<const float4*>(Abase + (size_t)arow * Dk + ac4);
    ra1 = *reinterpret_cast<const float4*>(Abase + (size_t)(arow + 64) * Dk + ac4);
    if (bvalid) {
        rb0 = *reinterpret_cast<const float4*>(Wp + (size_t)bkr * Cn + bcol);
        rb1 = *reinterpret_cast<const float4*>(Wp + (size_t)(bkr + 8) * Cn + bcol);
    } else {
        rb0 = make_float4(0.f, 0.f, 0.f, 0.f);
        rb1 = rb0;
    }
    // store into buffer 0 (with round-to-nearest tf32 conversion)
    {
        float4 c;
        c.x = to_tf32(ra0.x); c.y = to_tf32(ra0.y); c.z = to_tf32(ra0.z); c.w = to_tf32(ra0.w);
        *reinterpret_cast<float4*>(&As[0][arow * LDA + ac4]) = c;
        c.x = to_tf32(ra1.x); c.y = to_tf32(ra1.y); c.z = to_tf32(ra1.z); c.w = to_tf32(ra1.w);
        *reinterpret_cast<float4*>(&As[0][(arow + 64) * LDA + ac4]) = c;
        c.x = to_tf32(rb0.x); c.y = to_tf32(rb0.y); c.z = to_tf32(rb0.z); c.w = to_tf32(rb0.w);
        *reinterpret_cast<float4*>(&Bs[0][bkr * LDB + bc4]) = c;
        c.x = to_tf32(rb1.x); c.y = to_tf32(rb1.y); c.z = to_tf32(rb1.z); c.w = to_tf32(rb1.w);
        *reinterpret_cast<float4*>(&Bs[0][(bkr + 8) * LDB + bc4]) = c;
    }
    __syncthreads();

    const int nIter = Dk / BKT;   // 32
    for (int it = 0; it < nIter; ++it) {
        const int cur = it & 1;
        if (it + 1 < nIter) {
            const int kb = (it + 1) * BKT;
            ra0 = *reinterpret_cast<const float4*>(Abase + (size_t)arow * Dk + kb + ac4);
            ra1 = *reinterpret_cast<const float4*>(Abase + (size_t)(arow + 64) * Dk + kb + ac4);
            if (bvalid) {
                rb0 = *reinterpret_cast<const float4*>(Wp + (size_t)(kb + bkr) * Cn + bcol);
                rb1 = *reinterpret_cast<const float4*>(Wp + (size_t)(kb + bkr + 8) * Cn + bcol);
            }
        }

        // compute on buffer `cur`
        #pragma unroll
        for (int kk = 0; kk < BKT; kk += 8) {
            uint32_t af[4][4];
            uint32_t bf[4][2];
            #pragma unroll
            for (int mt = 0; mt < 4; ++mt) {
                const int m = wm * 64 + mt * 16 + g;
                const float* A0 = &As[cur][m * LDA + kk + t];
                af[mt][0] = __float_as_uint(A0[0]);
                af[mt][1] = __float_as_uint(A0[8 * LDA]);
                af[mt][2] = __float_as_uint(A0[4]);
                af[mt][3] = __float_as_uint(A0[8 * LDA + 4]);
            }
            #pragma unroll
            for (int nt = 0; nt < 4; ++nt) {
                const int n = wn * 32 + nt * 8 + g;
                const float* B0 = &Bs[cur][(kk + t) * LDB + n];
                bf[nt][0] = __float_as_uint(B0[0]);
                bf[nt][1] = __float_as_uint(B0[4 * LDB]);
            }
            #pragma unroll
            for (int mt = 0; mt < 4; ++mt)
                #pragma unroll
                for (int nt = 0; nt < 4; ++nt)
                    mma8(acc[mt][nt], af[mt], bf[nt]);
        }

        if (it + 1 < nIter) {
            const int nxt = cur ^ 1;
            float4 c;
            c.x = to_tf32(ra0.x); c.y = to_tf32(ra0.y); c.z = to_tf32(ra0.z); c.w = to_tf32(ra0.w);
            *reinterpret_cast<float4*>(&As[nxt][arow * LDA + ac4]) = c;
            c.x = to_tf32(ra1.x); c.y = to_tf32(ra1.y); c.z = to_tf32(ra1.z); c.w = to_tf32(ra1.w);
            *reinterpret_cast<float4*>(&As[nxt][(arow + 64) * LDA + ac4]) = c;
            c.x = to_tf32(rb0.x); c.y = to_tf32(rb0.y); c.z = to_tf32(rb0.z); c.w = to_tf32(rb0.w);
            *reinterpret_cast<float4*>(&Bs[nxt][bkr * LDB + bc4]) = c;
            c.x = to_tf32(rb1.x); c.y = to_tf32(rb1.y); c.z = to_tf32(rb1.z); c.w = to_tf32(rb1.w);
            *reinterpret_cast<float4*>(&Bs[nxt][(bkr + 8) * LDB + bc4]) = c;
            __syncthreads();
        }
    }

    // -------- fused epilogue: scale by 1/||w_c||, clip, store, accumulate exp-sums --------
    float rsum[4][2];
    #pragma unroll
    for (int mt = 0; mt < 4; ++mt) { rsum[mt][0] = 0.0f; rsum[mt][1] = 0.0f; }

    #pragma unroll
    for (int mt = 0; mt < 4; ++mt) {
        const int gr0 = bM + wm * 64 + mt * 16 + g;
        #pragma unroll
        for (int nt = 0; nt < 4; ++nt) {
            const int gc = bN + wn * 32 + nt * 8 + t * 2;
            if (gc < Cn) {
                const float iw0 = g_winv[gc];
                const float iw1 = g_winv[gc + 1];
                float c0 = fminf(fmaxf(acc[mt][nt][0] * iw0, -1.0f), 1.0f);
                float c1 = fminf(fmaxf(acc[mt][nt][1] * iw1, -1.0f), 1.0f);
                float c2 = fminf(fmaxf(acc[mt][nt][2] * iw0, -1.0f), 1.0f);
                float c3 = fminf(fmaxf(acc[mt][nt][3] * iw1, -1.0f), 1.0f);
                *reinterpret_cast<float2*>(&outc[(size_t)gr0 * Cn + gc]) = make_float2(c0, c1);
                *reinterpret_cast<float2*>(&outc[(size_t)(gr0 + 8) * Cn + gc]) = make_float2(c2, c3);
                rsum[mt][0] += __expf(S_s * c0) + __expf(S_s * c1);
                rsum[mt][1] += __expf(S_s * c2) + __expf(S_s * c3);
            }
        }
    }
    // reduce across the 4 lanes of each quad (same rows, different columns)
    #pragma unroll
    for (int mt = 0; mt < 4; ++mt) {
        #pragma unroll
        for (int h = 0; h < 2; ++h) {
            float v = rsum[mt][h];
            v += __shfl_xor_sync(0xffffffffu, v, 1);
            v += __shfl_xor_sync(0xffffffffu, v, 2);
            if (t == 0) {
                const int gr = bM + wm * 64 + mt * 16 + g + h * 8;
                atomicAdd(&g_rowsum[gr], v);
            }
        }
    }
}

// ---------------- kernel 4: per-row loss, mean, scalar out ----------------
__global__ void loss_kernel(const float* __restrict__ cosp_param,
                            const int* __restrict__ lbl32,
                            float* __restrict__ loss_out) {
    const float* cosp = cosp_param ? cosp_param : g_cos_scratch;
    const int b = threadIdx.x;   // 1024 threads, one block

    // detect label dtype: int64 labels (< 2^31) have all-zero high words
    __shared__ int nz;
    if (b == 0) nz = 0;
    __syncthreads();
    if (b < 512 && lbl32[2 * b + 1] != 0) atomicOr(&nz, 1);
    __syncthreads();

    int label;
    if (nz == 0) label = (int)(reinterpret_cast<const long long*>(lbl32)[b]);
    else         label = lbl32[b];

    const float tgt  = cosp[(size_t)b * Cn + label];
    const float excl = g_rowsum[b] - __expf(S_s * tgt);   // same exp as the GEMM epilogue
    const float num  = S_s * (tgt - M_m);
    const float L    = num - logf(expf(num) + excl);

    // block reduce sum over 1024 threads
    float v = L;
    #pragma unroll
    for (int o = 16; o > 0; o >>= 1) v += __shfl_xor_sync(0xffffffffu, v, o);
    __shared__ float red[32];
    if ((b & 31) == 0) red[b >> 5] = v;
    __syncthreads();
    if (b < 32) {
        float w = red[b];
        #pragma unroll
        for (int o = 16; o > 0; o >>= 1) w += __shfl_xor_sync(0xffffffffu, w, o);
        if (b == 0) loss_out[0] = -(w / (float)Bm);
    }
}

// ---------------- launch ----------------
extern "C" void kernel_launch(void* const* d_in, const int* in_sizes, int n_in,
                              void* d_out, int out_size) {
    const float* x   = (const float*)d_in[0];
    const float* W   = (const float*)d_in[1];
    const int*   lbl = (const int*)d_in[2];
    float* out = (float*)d_out;

    const long long BC = (long long)Bm * (long long)Cn;   // 102,400,000
    const bool cos_in_out = ((long long)out_size >= BC);

    normalize_x_kernel<<<Bm, 128>>>(x);
    wnorm_kernel<<<(Cn + 255) / 256, 256>>>(W);

    dim3 gg((Cn + BNT - 1) / BNT, Bm / BMT);   // (782, 8)
    gemm_cos_kernel<<<gg, 256>>>(W, cos_in_out ? out : nullptr);

    if (!cos_in_out) {
        // output holds only the loss
        if (out_size >= 1) loss_kernel<<<1, Bm>>>(nullptr, lbl, out);
    } else if ((long long)out_size >= BC + 1) {
        loss_kernel<<<1, Bm>>>(out, lbl, out + BC);
    }
}

// round 3
// speedup vs baseline: 1.0004x; 1.0004x over previous
#include <cuda_runtime.h>
#include <cstdint>
#include <cstddef>

// ---------------- problem constants ----------------
static constexpr int Bm = 1024;     // batch rows
static constexpr int Dk = 512;      // feature dim (K)
static constexpr int Cn = 100000;   // classes (N)
static constexpr float S_s = 30.0f;
static constexpr float M_m = 0.4f;

// ---------------- device scratch (no runtime allocation allowed) ----------------
__device__ float g_Xn[Bm * Dk];                       // normalized x
__device__ float g_winv[Cn];                          // 1 / ||W[:,c]||
__device__ float g_rowsum[Bm];                        // sum_c exp(S*cos)
__device__ float g_cos_scratch[(size_t)Bm * (size_t)Cn]; // only used if d_out can't hold cossim

// ---------------- helpers ----------------
__device__ __forceinline__ float to_tf32(float x) {
    uint32_t u;
    asm("cvt.rna.tf32.f32 %0, %1;" : "=r"(u) : "f"(x));
    return __uint_as_float(u);
}

__device__ __forceinline__ void mma8(float* d, const uint32_t* a, const uint32_t* b) {
    asm volatile(
        "mma.sync.aligned.m16n8k8.row.col.f32.tf32.tf32.f32 "
        "{%0,%1,%2,%3}, {%4,%5,%6,%7}, {%8,%9}, {%0,%1,%2,%3};\n"
        : "+f"(d[0]), "+f"(d[1]), "+f"(d[2]), "+f"(d[3])
        : "r"(a[0]), "r"(a[1]), "r"(a[2]), "r"(a[3]), "r"(b[0]), "r"(b[1]));
}

// ---------------- kernel 1: L2-normalize rows of x; zero rowsum ----------------
__global__ void normalize_x_kernel(const float* __restrict__ x) {
    const int b = blockIdx.x;           // 1024 blocks
    const int t = threadIdx.x;          // 128 threads
    float4 v = reinterpret_cast<const float4*>(x + (size_t)b * Dk)[t];
    float ss = v.x * v.x + v.y * v.y + v.z * v.z + v.w * v.w;
    #pragma unroll
    for (int o = 16; o > 0; o >>= 1) ss += __shfl_xor_sync(0xffffffffu, ss, o);
    __shared__ float ws[4];
    if ((t & 31) == 0) ws[t >> 5] = ss;
    __syncthreads();
    const float tot = ws[0] + ws[1] + ws[2] + ws[3];
    const float inv = 1.0f / fmaxf(sqrtf(tot), 1e-12f);
    float4 o4;
    o4.x = v.x * inv; o4.y = v.y * inv; o4.z = v.z * inv; o4.w = v.w * inv;
    reinterpret_cast<float4*>(g_Xn + (size_t)b * Dk)[t] = o4;
    if (t == 0) g_rowsum[b] = 0.0f;
}

// ---------------- kernel 2: per-column inverse norms of W ----------------
__global__ void wnorm_kernel(const float* __restrict__ Wp) {
    const int c = blockIdx.x * blockDim.x + threadIdx.x;
    if (c >= Cn) return;
    float ss = 0.0f;
    #pragma unroll 8
    for (int d = 0; d < Dk; ++d) {
        const float w = Wp[(size_t)d * Cn + c];
        ss = fmaf(w, w, ss);
    }
    g_winv[c] = 1.0f / fmaxf(sqrtf(ss), 1e-12f);
}

// ---------------- kernel 3: TF32 GEMM + fused AM-Softmax epilogue ----------------
#define BMT 128
#define BNT 128
#define BKT 16
#define LDA 20      // BK + 4  -> conflict-free A fragment loads
#define LDB 136     // BN + 8  -> conflict-free B fragment loads

__global__ void __launch_bounds__(256, 2)
gemm_cos_kernel(const float* __restrict__ Wp, float* __restrict__ outp) {
    __shared__ __align__(16) float As[2][BMT * LDA];
    __shared__ __align__(16) float Bs[2][BKT * LDB];

    float* __restrict__ outc = outp ? outp : g_cos_scratch;

    const int tid  = threadIdx.x;
    const int lane = tid & 31;
    const int g    = lane >> 2;
    const int t    = lane & 3;
    const int warp = tid >> 5;
    const int wm   = warp & 1;    // 2 warps in M
    const int wn   = warp >> 1;   // 4 warps in N
    const int bN   = blockIdx.x * BNT;
    const int bM   = blockIdx.y * BMT;

    // global-load coordinates (per thread)
    const int arow = tid >> 2;          // 0..63 (+64 for second chunk)
    const int ac4  = (tid & 3) * 4;     // k offset within BK
    const int bkr  = tid >> 5;          // 0..7  (+8 for second chunk)
    const int bc4  = (tid & 31) * 4;    // col offset within BN
    const int bcol = bN + bc4;
    const bool bvalid = (bcol < Cn);

    float acc[4][4][4];
    #pragma unroll
    for (int i = 0; i < 4; ++i)
        #pragma unroll
        for (int j = 0; j < 4; ++j)
            #pragma unroll
            for (int k = 0; k < 4; ++k) acc[i][j][k] = 0.0f;

    const float* Abase = g_Xn + (size_t)bM * Dk;

    float4 ra0, ra1, rb0, rb1;
    // prologue: load k-chunk 0
    ra0 = *reinterpret_cast<const float4*>(Abase + (size_t)arow * Dk + ac4);
    ra1 = *reinterpret_cast<const float4*>(Abase + (size_t)(arow + 64) * Dk + ac4);
    if (bvalid) {
        rb0 = *reinterpret_cast<const float4*>(Wp + (size_t)bkr * Cn + bcol);
        rb1 = *reinterpret_cast<const float4*>(Wp + (size_t)(bkr + 8) * Cn + bcol);
    } else {
        rb0 = make_float4(0.f, 0.f, 0.f, 0.f);
        rb1 = rb0;
    }
    // store into buffer 0 (with round-to-nearest tf32 conversion)
    {
        float4 c;
        c.x = to_tf32(ra0.x); c.y = to_tf32(ra0.y); c.z = to_tf32(ra0.z); c.w = to_tf32(ra0.w);
        *reinterpret_cast<float4*>(&As[0][arow * LDA + ac4]) = c;
        c.x = to_tf32(ra1.x); c.y = to_tf32(ra1.y); c.z = to_tf32(ra1.z); c.w = to_tf32(ra1.w);
        *reinterpret_cast<float4*>(&As[0][(arow + 64) * LDA + ac4]) = c;
        c.x = to_tf32(rb0.x); c.y = to_tf32(rb0.y); c.z = to_tf32(rb0.z); c.w = to_tf32(rb0.w);
        *reinterpret_cast<float4*>(&Bs[0][bkr * LDB + bc4]) = c;
        c.x = to_tf32(rb1.x); c.y = to_tf32(rb1.y); c.z = to_tf32(rb1.z); c.w = to_tf32(rb1.w);
        *reinterpret_cast<float4*>(&Bs[0][(bkr + 8) * LDB + bc4]) = c;
    }
    __syncthreads();

    const int nIter = Dk / BKT;   // 32
    for (int it = 0; it < nIter; ++it) {
        const int cur = it & 1;
        if (it + 1 < nIter) {
            const int kb = (it + 1) * BKT;
            ra0 = *reinterpret_cast<const float4*>(Abase + (size_t)arow * Dk + kb + ac4);
            ra1 = *reinterpret_cast<const float4*>(Abase + (size_t)(arow + 64) * Dk + kb + ac4);
            if (bvalid) {
                rb0 = *reinterpret_cast<const float4*>(Wp + (size_t)(kb + bkr) * Cn + bcol);
                rb1 = *reinterpret_cast<const float4*>(Wp + (size_t)(kb + bkr + 8) * Cn + bcol);
            }
        }

        // compute on buffer `cur`
        #pragma unroll
        for (int kk = 0; kk < BKT; kk += 8) {
            uint32_t af[4][4];
            uint32_t bf[4][2];
            #pragma unroll
            for (int mt = 0; mt < 4; ++mt) {
                const int m = wm * 64 + mt * 16 + g;
                const float* A0 = &As[cur][m * LDA + kk + t];
                af[mt][0] = __float_as_uint(A0[0]);
                af[mt][1] = __float_as_uint(A0[8 * LDA]);
                af[mt][2] = __float_as_uint(A0[4]);
                af[mt][3] = __float_as_uint(A0[8 * LDA + 4]);
            }
            #pragma unroll
            for (int nt = 0; nt < 4; ++nt) {
                const int n = wn * 32 + nt * 8 + g;
                const float* B0 = &Bs[cur][(kk + t) * LDB + n];
                bf[nt][0] = __float_as_uint(B0[0]);
                bf[nt][1] = __float_as_uint(B0[4 * LDB]);
            }
            #pragma unroll
            for (int mt = 0; mt < 4; ++mt)
                #pragma unroll
                for (int nt = 0; nt < 4; ++nt)
                    mma8(acc[mt][nt], af[mt], bf[nt]);
        }

        if (it + 1 < nIter) {
            const int nxt = cur ^ 1;
            float4 c;
            c.x = to_tf32(ra0.x); c.y = to_tf32(ra0.y); c.z = to_tf32(ra0.z); c.w = to_tf32(ra0.w);
            *reinterpret_cast<float4*>(&As[nxt][arow * LDA + ac4]) = c;
            c.x = to_tf32(ra1.x); c.y = to_tf32(ra1.y); c.z = to_tf32(ra1.z); c.w = to_tf32(ra1.w);
            *reinterpret_cast<float4*>(&As[nxt][(arow + 64) * LDA + ac4]) = c;
            c.x = to_tf32(rb0.x); c.y = to_tf32(rb0.y); c.z = to_tf32(rb0.z); c.w = to_tf32(rb0.w);
            *reinterpret_cast<float4*>(&Bs[nxt][bkr * LDB + bc4]) = c;
            c.x = to_tf32(rb1.x); c.y = to_tf32(rb1.y); c.z = to_tf32(rb1.z); c.w = to_tf32(rb1.w);
            *reinterpret_cast<float4*>(&Bs[nxt][(bkr + 8) * LDB + bc4]) = c;
            __syncthreads();
        }
    }

    // -------- fused epilogue: scale by 1/||w_c||, clip, store, accumulate exp-sums --------
    float rsum[4][2];
    #pragma unroll
    for (int mt = 0; mt < 4; ++mt) { rsum[mt][0] = 0.0f; rsum[mt][1] = 0.0f; }

    #pragma unroll
    for (int mt = 0; mt < 4; ++mt) {
        const int gr0 = bM + wm * 64 + mt * 16 + g;
        #pragma unroll
        for (int nt = 0; nt < 4; ++nt) {
            const int gc = bN + wn * 32 + nt * 8 + t * 2;
            if (gc < Cn) {
                const float iw0 = g_winv[gc];
                const float iw1 = g_winv[gc + 1];
                float c0 = fminf(fmaxf(acc[mt][nt][0] * iw0, -1.0f), 1.0f);
                float c1 = fminf(fmaxf(acc[mt][nt][1] * iw1, -1.0f), 1.0f);
                float c2 = fminf(fmaxf(acc[mt][nt][2] * iw0, -1.0f), 1.0f);
                float c3 = fminf(fmaxf(acc[mt][nt][3] * iw1, -1.0f), 1.0f);
                *reinterpret_cast<float2*>(&outc[(size_t)gr0 * Cn + gc]) = make_float2(c0, c1);
                *reinterpret_cast<float2*>(&outc[(size_t)(gr0 + 8) * Cn + gc]) = make_float2(c2, c3);
                rsum[mt][0] += __expf(S_s * c0) + __expf(S_s * c1);
                rsum[mt][1] += __expf(S_s * c2) + __expf(S_s * c3);
            }
        }
    }
    // reduce across the 4 lanes of each quad (same rows, different columns)
    #pragma unroll
    for (int mt = 0; mt < 4; ++mt) {
        #pragma unroll
        for (int h = 0; h < 2; ++h) {
            float v = rsum[mt][h];
            v += __shfl_xor_sync(0xffffffffu, v, 1);
            v += __shfl_xor_sync(0xffffffffu, v, 2);
            if (t == 0) {
                const int gr = bM + wm * 64 + mt * 16 + g + h * 8;
                atomicAdd(&g_rowsum[gr], v);
            }
        }
    }
}

// ---------------- kernel 4: per-row loss, mean, scalar out ----------------
__global__ void loss_kernel(const float* __restrict__ cosp_param,
                            const int* __restrict__ lbl32,
                            float* __restrict__ loss_out) {
    const float* cosp = cosp_param ? cosp_param : g_cos_scratch;
    const int b = threadIdx.x;   // 1024 threads, one block

    // detect label dtype: int64 labels (< 2^31) have all-zero high words
    __shared__ int nz;
    if (b == 0) nz = 0;
    __syncthreads();
    if (b < 512 && lbl32[2 * b + 1] != 0) atomicOr(&nz, 1);
    __syncthreads();

    int label;
    if (nz == 0) label = (int)(reinterpret_cast<const long long*>(lbl32)[b]);
    else         label = lbl32[b];

    const float tgt  = cosp[(size_t)b * Cn + label];
    const float excl = g_rowsum[b] - __expf(S_s * tgt);   // same exp as the GEMM epilogue
    const float num  = S_s * (tgt - M_m);
    const float L    = num - logf(expf(num) + excl);

    // block reduce sum over 1024 threads
    float v = L;
    #pragma unroll
    for (int o = 16; o > 0; o >>= 1) v += __shfl_xor_sync(0xffffffffu, v, o);
    __shared__ float red[32];
    if ((b & 31) == 0) red[b >> 5] = v;
    __syncthreads();
    if (b < 32) {
        float w = red[b];
        #pragma unroll
        for (int o = 16; o > 0; o >>= 1) w += __shfl_xor_sync(0xffffffffu, w, o);
        if (b == 0) loss_out[0] = -(w / (float)Bm);
    }
}

// ---------------- launch ----------------
extern "C" void kernel_launch(void* const* d_in, const int* in_sizes, int n_in,
                              void* d_out, int out_size) {
    const float* x   = (const float*)d_in[0];
    const float* W   = (const float*)d_in[1];
    const int*   lbl = (const int*)d_in[2];
    float* out = (float*)d_out;

    const long long BC = (long long)Bm * (long long)Cn;   // 102,400,000
    const bool cos_in_out = ((long long)out_size >= BC);

    normalize_x_kernel<<<Bm, 128>>>(x);
    wnorm_kernel<<<(Cn + 255) / 256, 256>>>(W);

    dim3 gg((Cn + BNT - 1) / BNT, Bm / BMT);   // (782, 8)
    gemm_cos_kernel<<<gg, 256>>>(W, cos_in_out ? out : nullptr);

    if (!cos_in_out) {
        // output holds only the loss
        if (out_size >= 1) loss_kernel<<<1, Bm>>>(nullptr, lbl, out);
    } else if ((long long)out_size >= BC + 1) {
        loss_kernel<<<1, Bm>>>(out, lbl, out + BC);
    }
}

// round 4
// speedup vs baseline: 1.0004x; 1.0001x over previous
#include <cuda_runtime.h>
#include <cstdint>
#include <cstddef>

// ---------------- problem constants ----------------
static constexpr int Bm = 1024;     // batch rows
static constexpr int Dk = 512;      // feature dim (K)
static constexpr int Cn = 100000;   // classes (N)
static constexpr float S_s = 30.0f;
static constexpr float M_m = 0.4f;

// ---------------- device scratch (no runtime allocation allowed) ----------------
__device__ float g_Xn[Bm * Dk];                       // normalized x
__device__ float g_winv[Cn];                          // 1 / ||W[:,c]||
__device__ float g_rowsum[Bm];                        // sum_c exp(S*cos)
__device__ float g_cos_scratch[(size_t)Bm * (size_t)Cn]; // only used if d_out can't hold cossim

// ---------------- helpers ----------------
__device__ __forceinline__ float to_tf32(float x) {
    uint32_t u;
    asm("cvt.rna.tf32.f32 %0, %1;" : "=r"(u) : "f"(x));
    return __uint_as_float(u);
}

__device__ __forceinline__ void mma8(float* d, const uint32_t* a, const uint32_t* b) {
    asm volatile(
        "mma.sync.aligned.m16n8k8.row.col.f32.tf32.tf32.f32 "
        "{%0,%1,%2,%3}, {%4,%5,%6,%7}, {%8,%9}, {%0,%1,%2,%3};\n"
        : "+f"(d[0]), "+f"(d[1]), "+f"(d[2]), "+f"(d[3])
        : "r"(a[0]), "r"(a[1]), "r"(a[2]), "r"(a[3]), "r"(b[0]), "r"(b[1]));
}

// ---------------- kernel 1: L2-normalize rows of x; zero rowsum ----------------
__global__ void normalize_x_kernel(const float* __restrict__ x) {
    const int b = blockIdx.x;           // 1024 blocks
    const int t = threadIdx.x;          // 128 threads
    float4 v = reinterpret_cast<const float4*>(x + (size_t)b * Dk)[t];
    float ss = v.x * v.x + v.y * v.y + v.z * v.z + v.w * v.w;
    #pragma unroll
    for (int o = 16; o > 0; o >>= 1) ss += __shfl_xor_sync(0xffffffffu, ss, o);
    __shared__ float ws[4];
    if ((t & 31) == 0) ws[t >> 5] = ss;
    __syncthreads();
    const float tot = ws[0] + ws[1] + ws[2] + ws[3];
    const float inv = 1.0f / fmaxf(sqrtf(tot), 1e-12f);
    float4 o4;
    o4.x = v.x * inv; o4.y = v.y * inv; o4.z = v.z * inv; o4.w = v.w * inv;
    reinterpret_cast<float4*>(g_Xn + (size_t)b * Dk)[t] = o4;
    if (t == 0) g_rowsum[b] = 0.0f;
}

// ---------------- kernel 2: per-column inverse norms of W ----------------
__global__ void wnorm_kernel(const float* __restrict__ Wp) {
    const int c = blockIdx.x * blockDim.x + threadIdx.x;
    if (c >= Cn) return;
    float ss = 0.0f;
    #pragma unroll 8
    for (int d = 0; d < Dk; ++d) {
        const float w = Wp[(size_t)d * Cn + c];
        ss = fmaf(w, w, ss);
    }
    g_winv[c] = 1.0f / fmaxf(sqrtf(ss), 1e-12f);
}

// ---------------- kernel 3: TF32 GEMM + fused AM-Softmax epilogue ----------------
#define BMT 128
#define BNT 128
#define BKT 16
#define LDA 20      // BK + 4  -> conflict-free A fragment loads
#define LDB 136     // BN + 8  -> conflict-free B fragment loads

__global__ void __launch_bounds__(256, 2)
gemm_cos_kernel(const float* __restrict__ Wp, float* __restrict__ outp) {
    __shared__ __align__(16) float As[2][BMT * LDA];
    __shared__ __align__(16) float Bs[2][BKT * LDB];

    float* __restrict__ outc = outp ? outp : g_cos_scratch;

    const int tid  = threadIdx.x;
    const int lane = tid & 31;
    const int g    = lane >> 2;
    const int t    = lane & 3;
    const int warp = tid >> 5;
    const int wm   = warp & 1;    // 2 warps in M
    const int wn   = warp >> 1;   // 4 warps in N
    const int bN   = blockIdx.x * BNT;
    const int bM   = blockIdx.y * BMT;

    // global-load coordinates (per thread)
    const int arow = tid >> 2;          // 0..63 (+64 for second chunk)
    const int ac4  = (tid & 3) * 4;     // k offset within BK
    const int bkr  = tid >> 5;          // 0..7  (+8 for second chunk)
    const int bc4  = (tid & 31) * 4;    // col offset within BN
    const int bcol = bN + bc4;
    const bool bvalid = (bcol < Cn);

    float acc[4][4][4];
    #pragma unroll
    for (int i = 0; i < 4; ++i)
        #pragma unroll
        for (int j = 0; j < 4; ++j)
            #pragma unroll
            for (int k = 0; k < 4; ++k) acc[i][j][k] = 0.0f;

    const float* Abase = g_Xn + (size_t)bM * Dk;

    float4 ra0, ra1, rb0, rb1;
    // prologue: load k-chunk 0
    ra0 = *reinterpret_cast<const float4*>(Abase + (size_t)arow * Dk + ac4);
    ra1 = *reinterpret_cast<const float4*>(Abase + (size_t)(arow + 64) * Dk + ac4);
    if (bvalid) {
        rb0 = *reinterpret_cast<const float4*>(Wp + (size_t)bkr * Cn + bcol);
        rb1 = *reinterpret_cast<const float4*>(Wp + (size_t)(bkr + 8) * Cn + bcol);
    } else {
        rb0 = make_float4(0.f, 0.f, 0.f, 0.f);
        rb1 = rb0;
    }
    // store into buffer 0 (with round-to-nearest tf32 conversion)
    {
        float4 c;
        c.x = to_tf32(ra0.x); c.y = to_tf32(ra0.y); c.z = to_tf32(ra0.z); c.w = to_tf32(ra0.w);
        *reinterpret_cast<float4*>(&As[0][arow * LDA + ac4]) = c;
        c.x = to_tf32(ra1.x); c.y = to_tf32(ra1.y); c.z = to_tf32(ra1.z); c.w = to_tf32(ra1.w);
        *reinterpret_cast<float4*>(&As[0][(arow + 64) * LDA + ac4]) = c;
        c.x = to_tf32(rb0.x); c.y = to_tf32(rb0.y); c.z = to_tf32(rb0.z); c.w = to_tf32(rb0.w);
        *reinterpret_cast<float4*>(&Bs[0][bkr * LDB + bc4]) = c;
        c.x = to_tf32(rb1.x); c.y = to_tf32(rb1.y); c.z = to_tf32(rb1.z); c.w = to_tf32(rb1.w);
        *reinterpret_cast<float4*>(&Bs[0][(bkr + 8) * LDB + bc4]) = c;
    }
    __syncthreads();

    const int nIter = Dk / BKT;   // 32
    for (int it = 0; it < nIter; ++it) {
        const int cur = it & 1;
        if (it + 1 < nIter) {
            const int kb = (it + 1) * BKT;
            ra0 = *reinterpret_cast<const float4*>(Abase + (size_t)arow * Dk + kb + ac4);
            ra1 = *reinterpret_cast<const float4*>(Abase + (size_t)(arow + 64) * Dk + kb + ac4);
            if (bvalid) {
                rb0 = *reinterpret_cast<const float4*>(Wp + (size_t)(kb + bkr) * Cn + bcol);
                rb1 = *reinterpret_cast<const float4*>(Wp + (size_t)(kb + bkr + 8) * Cn + bcol);
            }
        }

        // compute on buffer `cur`
        #pragma unroll
        for (int kk = 0; kk < BKT; kk += 8) {
            uint32_t af[4][4];
            uint32_t bf[4][2];
            #pragma unroll
            for (int mt = 0; mt < 4; ++mt) {
                const int m = wm * 64 + mt * 16 + g;
                const float* A0 = &As[cur][m * LDA + kk + t];
                af[mt][0] = __float_as_uint(A0[0]);
                af[mt][1] = __float_as_uint(A0[8 * LDA]);
                af[mt][2] = __float_as_uint(A0[4]);
                af[mt][3] = __float_as_uint(A0[8 * LDA + 4]);
            }
            #pragma unroll
            for (int nt = 0; nt < 4; ++nt) {
                const int n = wn * 32 + nt * 8 + g;
                const float* B0 = &Bs[cur][(kk + t) * LDB + n];
                bf[nt][0] = __float_as_uint(B0[0]);
                bf[nt][1] = __float_as_uint(B0[4 * LDB]);
            }
            #pragma unroll
            for (int mt = 0; mt < 4; ++mt)
                #pragma unroll
                for (int nt = 0; nt < 4; ++nt)
                    mma8(acc[mt][nt], af[mt], bf[nt]);
        }

        if (it + 1 < nIter) {
            const int nxt = cur ^ 1;
            float4 c;
            c.x = to_tf32(ra0.x); c.y = to_tf32(ra0.y); c.z = to_tf32(ra0.z); c.w = to_tf32(ra0.w);
            *reinterpret_cast<float4*>(&As[nxt][arow * LDA + ac4]) = c;
            c.x = to_tf32(ra1.x); c.y = to_tf32(ra1.y); c.z = to_tf32(ra1.z); c.w = to_tf32(ra1.w);
            *reinterpret_cast<float4*>(&As[nxt][(arow + 64) * LDA + ac4]) = c;
            c.x = to_tf32(rb0.x); c.y = to_tf32(rb0.y); c.z = to_tf32(rb0.z); c.w = to_tf32(rb0.w);
            *reinterpret_cast<float4*>(&Bs[nxt][bkr * LDB + bc4]) = c;
            c.x = to_tf32(rb1.x); c.y = to_tf32(rb1.y); c.z = to_tf32(rb1.z); c.w = to_tf32(rb1.w);
            *reinterpret_cast<float4*>(&Bs[nxt][(bkr + 8) * LDB + bc4]) = c;
            __syncthreads();
        }
    }

    // -------- fused epilogue: scale by 1/||w_c||, clip, store, accumulate exp-sums --------
    float rsum[4][2];
    #pragma unroll
    for (int mt = 0; mt < 4; ++mt) { rsum[mt][0] = 0.0f; rsum[mt][1] = 0.0f; }

    #pragma unroll
    for (int mt = 0; mt < 4; ++mt) {
        const int gr0 = bM + wm * 64 + mt * 16 + g;
        #pragma unroll
        for (int nt = 0; nt < 4; ++nt) {
            const int gc = bN + wn * 32 + nt * 8 + t * 2;
            if (gc < Cn) {
                const float iw0 = g_winv[gc];
                const float iw1 = g_winv[gc + 1];
                float c0 = fminf(fmaxf(acc[mt][nt][0] * iw0, -1.0f), 1.0f);
                float c1 = fminf(fmaxf(acc[mt][nt][1] * iw1, -1.0f), 1.0f);
                float c2 = fminf(fmaxf(acc[mt][nt][2] * iw0, -1.0f), 1.0f);
                float c3 = fminf(fmaxf(acc[mt][nt][3] * iw1, -1.0f), 1.0f);
                *reinterpret_cast<float2*>(&outc[(size_t)gr0 * Cn + gc]) = make_float2(c0, c1);
                *reinterpret_cast<float2*>(&outc[(size_t)(gr0 + 8) * Cn + gc]) = make_float2(c2, c3);
                rsum[mt][0] += __expf(S_s * c0) + __expf(S_s * c1);
                rsum[mt][1] += __expf(S_s * c2) + __expf(S_s * c3);
            }
        }
    }
    // reduce across the 4 lanes of each quad (same rows, different columns)
    #pragma unroll
    for (int mt = 0; mt < 4; ++mt) {
        #pragma unroll
        for (int h = 0; h < 2; ++h) {
            float v = rsum[mt][h];
            v += __shfl_xor_sync(0xffffffffu, v, 1);
            v += __shfl_xor_sync(0xffffffffu, v, 2);
            if (t == 0) {
                const int gr = bM + wm * 64 + mt * 16 + g + h * 8;
                atomicAdd(&g_rowsum[gr], v);
            }
        }
    }
}

// ---------------- kernel 4: per-row loss, mean, scalar out ----------------
__global__ void loss_kernel(const float* __restrict__ cosp_param,
                            const int* __restrict__ lbl32,
                            float* __restrict__ loss_out) {
    const float* cosp = cosp_param ? cosp_param : g_cos_scratch;
    const int b = threadIdx.x;   // 1024 threads, one block

    // detect label dtype: int64 labels (< 2^31) have all-zero high words
    __shared__ int nz;
    if (b == 0) nz = 0;
    __syncthreads();
    if (b < 512 && lbl32[2 * b + 1] != 0) atomicOr(&nz, 1);
    __syncthreads();

    int label;
    if (nz == 0) label = (int)(reinterpret_cast<const long long*>(lbl32)[b]);
    else         label = lbl32[b];

    const float tgt  = cosp[(size_t)b * Cn + label];
    const float excl = g_rowsum[b] - __expf(S_s * tgt);   // same exp as the GEMM epilogue
    const float num  = S_s * (tgt - M_m);
    const float L    = num - logf(expf(num) + excl);

    // block reduce sum over 1024 threads
    float v = L;
    #pragma unroll
    for (int o = 16; o > 0; o >>= 1) v += __shfl_xor_sync(0xffffffffu, v, o);
    __shared__ float red[32];
    if ((b & 31) == 0) red[b >> 5] = v;
    __syncthreads();
    if (b < 32) {
        float w = red[b];
        #pragma unroll
        for (int o = 16; o > 0; o >>= 1) w += __shfl_xor_sync(0xffffffffu, w, o);
        if (b == 0) loss_out[0] = -(w / (float)Bm);
    }
}

// ---------------- launch ----------------
extern "C" void kernel_launch(void* const* d_in, const int* in_sizes, int n_in,
                              void* d_out, int out_size) {
    const float* x   = (const float*)d_in[0];
    const float* W   = (const float*)d_in[1];
    const int*   lbl = (const int*)d_in[2];
    float* out = (float*)d_out;

    const long long BC = (long long)Bm * (long long)Cn;   // 102,400,000
    const bool cos_in_out = ((long long)out_size >= BC);

    normalize_x_kernel<<<Bm, 128>>>(x);
    wnorm_kernel<<<(Cn + 255) / 256, 256>>>(W);

    dim3 gg((Cn + BNT - 1) / BNT, Bm / BMT);   // (782, 8)
    gemm_cos_kernel<<<gg, 256>>>(W, cos_in_out ? out : nullptr);

    if (!cos_in_out) {
        // output holds only the loss
        if (out_size >= 1) loss_kernel<<<1, Bm>>>(nullptr, lbl, out);
    } else if ((long long)out_size >= BC + 1) {
        loss_kernel<<<1, Bm>>>(out, lbl, out + BC);
    }
}

// round 5
// speedup vs baseline: 1.0008x; 1.0003x over previous
#include <cuda_runtime.h>
#include <cstdint>
#include <cstddef>

// ---------------- problem constants ----------------
static constexpr int Bm = 1024;     // batch rows
static constexpr int Dk = 512;      // feature dim (K)
static constexpr int Cn = 100000;   // classes (N)
static constexpr float S_s = 30.0f;
static constexpr float M_m = 0.4f;

// ---------------- device scratch (no runtime allocation allowed) ----------------
__device__ float g_Xn[Bm * Dk];                       // normalized x
__device__ float g_winv[Cn];                          // 1 / ||W[:,c]||
__device__ float g_rowsum[Bm];                        // sum_c exp(S*cos)
__device__ float g_cos_scratch[(size_t)Bm * (size_t)Cn]; // only used if d_out can't hold cossim

// ---------------- helpers ----------------
__device__ __forceinline__ float to_tf32(float x) {
    uint32_t u;
    asm("cvt.rna.tf32.f32 %0, %1;" : "=r"(u) : "f"(x));
    return __uint_as_float(u);
}

__device__ __forceinline__ void mma8(float* d, const uint32_t* a, const uint32_t* b) {
    asm volatile(
        "mma.sync.aligned.m16n8k8.row.col.f32.tf32.tf32.f32 "
        "{%0,%1,%2,%3}, {%4,%5,%6,%7}, {%8,%9}, {%0,%1,%2,%3};\n"
        : "+f"(d[0]), "+f"(d[1]), "+f"(d[2]), "+f"(d[3])
        : "r"(a[0]), "r"(a[1]), "r"(a[2]), "r"(a[3]), "r"(b[0]), "r"(b[1]));
}

// ---------------- kernel 1: L2-normalize rows of x; zero rowsum ----------------
__global__ void normalize_x_kernel(const float* __restrict__ x) {
    const int b = blockIdx.x;           // 1024 blocks
    const int t = threadIdx.x;          // 128 threads
    float4 v = reinterpret_cast<const float4*>(x + (size_t)b * Dk)[t];
    float ss = v.x * v.x + v.y * v.y + v.z * v.z + v.w * v.w;
    #pragma unroll
    for (int o = 16; o > 0; o >>= 1) ss += __shfl_xor_sync(0xffffffffu, ss, o);
    __shared__ float ws[4];
    if ((t & 31) == 0) ws[t >> 5] = ss;
    __syncthreads();
    const float tot = ws[0] + ws[1] + ws[2] + ws[3];
    const float inv = 1.0f / fmaxf(sqrtf(tot), 1e-12f);
    float4 o4;
    o4.x = v.x * inv; o4.y = v.y * inv; o4.z = v.z * inv; o4.w = v.w * inv;
    reinterpret_cast<float4*>(g_Xn + (size_t)b * Dk)[t] = o4;
    if (t == 0) g_rowsum[b] = 0.0f;
}

// ---------------- kernel 2: per-column inverse norms of W ----------------
__global__ void wnorm_kernel(const float* __restrict__ Wp) {
    const int c = blockIdx.x * blockDim.x + threadIdx.x;
    if (c >= Cn) return;
    float ss = 0.0f;
    #pragma unroll 8
    for (int d = 0; d < Dk; ++d) {
        const float w = Wp[(size_t)d * Cn + c];
        ss = fmaf(w, w, ss);
    }
    g_winv[c] = 1.0f / fmaxf(sqrtf(ss), 1e-12f);
}

// ---------------- kernel 3: TF32 GEMM + fused AM-Softmax epilogue ----------------
#define BMT 128
#define BNT 128
#define BKT 16
#define LDA 20      // BK + 4  -> conflict-free A fragment loads
#define LDB 136     // BN + 8  -> conflict-free B fragment loads

__global__ void __launch_bounds__(256, 2)
gemm_cos_kernel(const float* __restrict__ Wp, float* __restrict__ outp) {
    __shared__ __align__(16) float As[2][BMT * LDA];
    __shared__ __align__(16) float Bs[2][BKT * LDB];

    float* __restrict__ outc = outp ? outp : g_cos_scratch;

    const int tid  = threadIdx.x;
    const int lane = tid & 31;
    const int g    = lane >> 2;
    const int t    = lane & 3;
    const int warp = tid >> 5;
    const int wm   = warp & 1;    // 2 warps in M
    const int wn   = warp >> 1;   // 4 warps in N
    const int bN   = blockIdx.x * BNT;
    const int bM   = blockIdx.y * BMT;

    // global-load coordinates (per thread)
    const int arow = tid >> 2;          // 0..63 (+64 for second chunk)
    const int ac4  = (tid & 3) * 4;     // k offset within BK
    const int bkr  = tid >> 5;          // 0..7  (+8 for second chunk)
    const int bc4  = (tid & 31) * 4;    // col offset within BN
    const int bcol = bN + bc4;
    const bool bvalid = (bcol < Cn);

    float acc[4][4][4];
    #pragma unroll
    for (int i = 0; i < 4; ++i)
        #pragma unroll
        for (int j = 0; j < 4; ++j)
            #pragma unroll
            for (int k = 0; k < 4; ++k) acc[i][j][k] = 0.0f;

    const float* Abase = g_Xn + (size_t)bM * Dk;

    float4 ra0, ra1, rb0, rb1;
    // prologue: load k-chunk 0
    ra0 = *reinterpret_cast<const float4*>(Abase + (size_t)arow * Dk + ac4);
    ra1 = *reinterpret_cast<const float4*>(Abase + (size_t)(arow + 64) * Dk + ac4);
    if (bvalid) {
        rb0 = *reinterpret_cast<const float4*>(Wp + (size_t)bkr * Cn + bcol);
        rb1 = *reinterpret_cast<const float4*>(Wp + (size_t)(bkr + 8) * Cn + bcol);
    } else {
        rb0 = make_float4(0.f, 0.f, 0.f, 0.f);
        rb1 = rb0;
    }
    // store into buffer 0 (with round-to-nearest tf32 conversion)
    {
        float4 c;
        c.x = to_tf32(ra0.x); c.y = to_tf32(ra0.y); c.z = to_tf32(ra0.z); c.w = to_tf32(ra0.w);
        *reinterpret_cast<float4*>(&As[0][arow * LDA + ac4]) = c;
        c.x = to_tf32(ra1.x); c.y = to_tf32(ra1.y); c.z = to_tf32(ra1.z); c.w = to_tf32(ra1.w);
        *reinterpret_cast<float4*>(&As[0][(arow + 64) * LDA + ac4]) = c;
        c.x = to_tf32(rb0.x); c.y = to_tf32(rb0.y); c.z = to_tf32(rb0.z); c.w = to_tf32(rb0.w);
        *reinterpret_cast<float4*>(&Bs[0][bkr * LDB + bc4]) = c;
        c.x = to_tf32(rb1.x); c.y = to_tf32(rb1.y); c.z = to_tf32(rb1.z); c.w = to_tf32(rb1.w);
        *reinterpret_cast<float4*>(&Bs[0][(bkr + 8) * LDB + bc4]) = c;
    }
    __syncthreads();

    const int nIter = Dk / BKT;   // 32
    for (int it = 0; it < nIter; ++it) {
        const int cur = it & 1;
        if (it + 1 < nIter) {
            const int kb = (it + 1) * BKT;
            ra0 = *reinterpret_cast<const float4*>(Abase + (size_t)arow * Dk + kb + ac4);
            ra1 = *reinterpret_cast<const float4*>(Abase + (size_t)(arow + 64) * Dk + kb + ac4);
            if (bvalid) {
                rb0 = *reinterpret_cast<const float4*>(Wp + (size_t)(kb + bkr) * Cn + bcol);
                rb1 = *reinterpret_cast<const float4*>(Wp + (size_t)(kb + bkr + 8) * Cn + bcol);
            }
        }

        // compute on buffer `cur`
        #pragma unroll
        for (int kk = 0; kk < BKT; kk += 8) {
            uint32_t af[4][4];
            uint32_t bf[4][2];
            #pragma unroll
            for (int mt = 0; mt < 4; ++mt) {
                const int m = wm * 64 + mt * 16 + g;
                const float* A0 = &As[cur][m * LDA + kk + t];
                af[mt][0] = __float_as_uint(A0[0]);
                af[mt][1] = __float_as_uint(A0[8 * LDA]);
                af[mt][2] = __float_as_uint(A0[4]);
                af[mt][3] = __float_as_uint(A0[8 * LDA + 4]);
            }
            #pragma unroll
            for (int nt = 0; nt < 4; ++nt) {
                const int n = wn * 32 + nt * 8 + g;
                const float* B0 = &Bs[cur][(kk + t) * LDB + n];
                bf[nt][0] = __float_as_uint(B0[0]);
                bf[nt][1] = __float_as_uint(B0[4 * LDB]);
            }
            #pragma unroll
            for (int mt = 0; mt < 4; ++mt)
                #pragma unroll
                for (int nt = 0; nt < 4; ++nt)
                    mma8(acc[mt][nt], af[mt], bf[nt]);
        }

        if (it + 1 < nIter) {
            const int nxt = cur ^ 1;
            float4 c;
            c.x = to_tf32(ra0.x); c.y = to_tf32(ra0.y); c.z = to_tf32(ra0.z); c.w = to_tf32(ra0.w);
            *reinterpret_cast<float4*>(&As[nxt][arow * LDA + ac4]) = c;
            c.x = to_tf32(ra1.x); c.y = to_tf32(ra1.y); c.z = to_tf32(ra1.z); c.w = to_tf32(ra1.w);
            *reinterpret_cast<float4*>(&As[nxt][(arow + 64) * LDA + ac4]) = c;
            c.x = to_tf32(rb0.x); c.y = to_tf32(rb0.y); c.z = to_tf32(rb0.z); c.w = to_tf32(rb0.w);
            *reinterpret_cast<float4*>(&Bs[nxt][bkr * LDB + bc4]) = c;
            c.x = to_tf32(rb1.x); c.y = to_tf32(rb1.y); c.z = to_tf32(rb1.z); c.w = to_tf32(rb1.w);
            *reinterpret_cast<float4*>(&Bs[nxt][(bkr + 8) * LDB + bc4]) = c;
            __syncthreads();
        }
    }

    // -------- fused epilogue: scale by 1/||w_c||, clip, store, accumulate exp-sums --------
    float rsum[4][2];
    #pragma unroll
    for (int mt = 0; mt < 4; ++mt) { rsum[mt][0] = 0.0f; rsum[mt][1] = 0.0f; }

    #pragma unroll
    for (int mt = 0; mt < 4; ++mt) {
        const int gr0 = bM + wm * 64 + mt * 16 + g;
        #pragma unroll
        for (int nt = 0; nt < 4; ++nt) {
            const int gc = bN + wn * 32 + nt * 8 + t * 2;
            if (gc < Cn) {
                const float iw0 = g_winv[gc];
                const float iw1 = g_winv[gc + 1];
                float c0 = fminf(fmaxf(acc[mt][nt][0] * iw0, -1.0f), 1.0f);
                float c1 = fminf(fmaxf(acc[mt][nt][1] * iw1, -1.0f), 1.0f);
                float c2 = fminf(fmaxf(acc[mt][nt][2] * iw0, -1.0f), 1.0f);
                float c3 = fminf(fmaxf(acc[mt][nt][3] * iw1, -1.0f), 1.0f);
                *reinterpret_cast<float2*>(&outc[(size_t)gr0 * Cn + gc]) = make_float2(c0, c1);
                *reinterpret_cast<float2*>(&outc[(size_t)(gr0 + 8) * Cn + gc]) = make_float2(c2, c3);
                rsum[mt][0] += __expf(S_s * c0) + __expf(S_s * c1);
                rsum[mt][1] += __expf(S_s * c2) + __expf(S_s * c3);
            }
        }
    }
    // reduce across the 4 lanes of each quad (same rows, different columns)
    #pragma unroll
    for (int mt = 0; mt < 4; ++mt) {
        #pragma unroll
        for (int h = 0; h < 2; ++h) {
            float v = rsum[mt][h];
            v += __shfl_xor_sync(0xffffffffu, v, 1);
            v += __shfl_xor_sync(0xffffffffu, v, 2);
            if (t == 0) {
                const int gr = bM + wm * 64 + mt * 16 + g + h * 8;
                atomicAdd(&g_rowsum[gr], v);
            }
        }
    }
}

// ---------------- kernel 4: per-row loss, mean, scalar out ----------------
__global__ void loss_kernel(const float* __restrict__ cosp_param,
                            const int* __restrict__ lbl32,
                            float* __restrict__ loss_out) {
    const float* cosp = cosp_param ? cosp_param : g_cos_scratch;
    const int b = threadIdx.x;   // 1024 threads, one block

    // detect label dtype: int64 labels (< 2^31) have all-zero high words
    __shared__ int nz;
    if (b == 0) nz = 0;
    __syncthreads();
    if (b < 512 && lbl32[2 * b + 1] != 0) atomicOr(&nz, 1);
    __syncthreads();

    int label;
    if (nz == 0) label = (int)(reinterpret_cast<const long long*>(lbl32)[b]);
    else         label = lbl32[b];

    const float tgt  = cosp[(size_t)b * Cn + label];
    const float excl = g_rowsum[b] - __expf(S_s * tgt);   // same exp as the GEMM epilogue
    const float num  = S_s * (tgt - M_m);
    const float L    = num - logf(expf(num) + excl);

    // block reduce sum over 1024 threads
    float v = L;
    #pragma unroll
    for (int o = 16; o > 0; o >>= 1) v += __shfl_xor_sync(0xffffffffu, v, o);
    __shared__ float red[32];
    if ((b & 31) == 0) red[b >> 5] = v;
    __syncthreads();
    if (b < 32) {
        float w = red[b];
        #pragma unroll
        for (int o = 16; o > 0; o >>= 1) w += __shfl_xor_sync(0xffffffffu, w, o);
        if (b == 0) loss_out[0] = -(w / (float)Bm);
    }
}

// ---------------- launch ----------------
extern "C" void kernel_launch(void* const* d_in, const int* in_sizes, int n_in,
                              void* d_out, int out_size) {
    const float* x   = (const float*)d_in[0];
    const float* W   = (const float*)d_in[1];
    const int*   lbl = (const int*)d_in[2];
    float* out = (float*)d_out;

    const long long BC = (long long)Bm * (long long)Cn;   // 102,400,000
    const bool cos_in_out = ((long long)out_size >= BC);

    normalize_x_kernel<<<Bm, 128>>>(x);
    wnorm_kernel<<<(Cn + 255) / 256, 256>>>(W);

    dim3 gg((Cn + BNT - 1) / BNT, Bm / BMT);   // (782, 8)
    gemm_cos_kernel<<<gg, 256>>>(W, cos_in_out ? out : nullptr);

    if (!cos_in_out) {
        // output holds only the loss
        if (out_size >= 1) loss_kernel<<<1, Bm>>>(nullptr, lbl, out);
    } else if ((long long)out_size >= BC + 1) {
        loss_kernel<<<1, Bm>>>(out, lbl, out + BC);
    }
}